// round 7
// baseline (speedup 1.0000x reference)
#include <cuda_runtime.h>
#include <math.h>

#define Nn 50000
#define Ee 800000
#define Hh 8
#define Dd 128

// ---------------- scratch (static device globals; no runtime alloc) ----------------
__device__ int   g_is64;
__device__ int   g_eidx[2 * Ee];         // normalized int32 edge index [src | dst]
__device__ int   g_rowcnt[Nn];
__device__ int   g_cursor[Nn];
__device__ int   g_rowptr[Nn + 1];
__device__ int   g_ssrc[Ee];
__device__ float g_sw[Ee];
__device__ float g_W0p[Dd * Dd];
__device__ float g_Wh0[Nn * Dd];
__device__ float g_es[Nn * Hh];
__device__ float g_ed[Nn * Hh];
__device__ float g_att[Ee * Hh];
__device__ float g_x1[Nn * Dd];          // GAT layer-0 output (post-ELU)
__device__ float g_y[Nn * 1024];         // per-head aggregated x1: [n][h][128]
__device__ float g_hg[Nn * Dd];          // GCN GEMM output
__device__ float g_x2[Nn * Dd];          // GCN layer-1 output
__device__ float g_x2b[Nn * Dd];         // GCN layer-2 output
__device__ float g_u1[Hh * Dd];
__device__ float g_v1[Hh * Dd];

// ---------------- edge-index dtype detection + normalization ----------------
// If the buffer is int64 (little-endian, values in [0, N) << 2^31), every odd
// int32 word is the zero high-half. If it is int32, odd words are random node
// indices; P(256 consecutive == 0) is negligible.
__global__ void k_detect(const int* __restrict__ ei32) {
    if (threadIdx.x == 0 && blockIdx.x == 0) {
        int is64 = 1;
        for (int i = 0; i < 256; i++)
            if (ei32[2 * i + 1] != 0) { is64 = 0; break; }
        g_is64 = is64;
    }
}

__global__ void k_convert(const int* __restrict__ ei32) {
    int i = blockIdx.x * blockDim.x + threadIdx.x;
    if (i >= 2 * Ee) return;
    g_eidx[i] = g_is64 ? ei32[2 * i] : ei32[i];
}

// ---------------- CSR build ----------------
__global__ void k_zero() {
    int i = blockIdx.x * blockDim.x + threadIdx.x;
    if (i < Nn) { g_rowcnt[i] = 0; g_cursor[i] = 0; }
}

__global__ void k_count() {
    int i = blockIdx.x * blockDim.x + threadIdx.x;
    if (i < Ee) atomicAdd(&g_rowcnt[g_eidx[Ee + i]], 1);
}

__global__ void k_scan() {  // single block, 1024 threads
    __shared__ int tmp[1024];
    __shared__ int s_off;
    int t = threadIdx.x;
    if (t == 0) { s_off = 0; g_rowptr[0] = 0; }
    __syncthreads();
    for (int base = 0; base < Nn; base += 1024) {
        int i = base + t;
        int v = (i < Nn) ? g_rowcnt[i] : 0;
        tmp[t] = v;
        __syncthreads();
        for (int d = 1; d < 1024; d <<= 1) {
            int add = (t >= d) ? tmp[t - d] : 0;
            __syncthreads();
            tmp[t] += add;
            __syncthreads();
        }
        if (i < Nn) g_rowptr[i + 1] = s_off + tmp[t];
        __syncthreads();
        if (t == 1023) s_off += tmp[1023];
        __syncthreads();
    }
}

__global__ void k_scatter(const float* __restrict__ w) {
    int i = blockIdx.x * blockDim.x + threadIdx.x;
    if (i >= Ee) return;
    int s = g_eidx[i];
    int d = g_eidx[Ee + i];
    int p = g_rowptr[d] + atomicAdd(&g_cursor[d], 1);
    g_ssrc[p] = s;
    g_sw[p]   = w[i];
}

// ---------------- weight prep ----------------
// W0 [8][128][16] -> W0p [128][128] with col = h*16+f
__global__ void k_packW0(const float* __restrict__ W0) {
    int i = blockIdx.x * blockDim.x + threadIdx.x;
    if (i >= Dd * Dd) return;
    int k = i >> 7, c = i & 127;
    int h = c >> 4, f = c & 15;
    g_W0p[k * Dd + c] = W0[h * (Dd * 16) + k * 16 + f];
}

// u1[h][k] = sum_f W1[h][k][f]*a_src[h][f]   (and v1 with a_dst)
__global__ void k_uv1(const float* __restrict__ W1,
                      const float* __restrict__ a_s, const float* __restrict__ a_d) {
    int i = blockIdx.x * blockDim.x + threadIdx.x;
    if (i >= Hh * Dd) return;
    int h = i >> 7, k = i & 127;
    const float* w = &W1[h * Dd * Dd + k * Dd];
    float su = 0.f, sv = 0.f;
    #pragma unroll 8
    for (int f = 0; f < Dd; f++) {
        float v = __ldg(&w[f]);
        su = fmaf(v, __ldg(&a_s[h * Dd + f]), su);
        sv = fmaf(v, __ldg(&a_d[h * Dd + f]), sv);
    }
    g_u1[i] = su; g_v1[i] = sv;
}

// ---------------- es / ed ----------------
__global__ void k_esed0(const float* __restrict__ a_s, const float* __restrict__ a_d) {
    int i = blockIdx.x * blockDim.x + threadIdx.x;
    if (i >= Nn * Hh) return;
    int n = i >> 3, h = i & 7;
    const float* w = &g_Wh0[n * Dd + h * 16];
    float s = 0.f, d = 0.f;
    #pragma unroll
    for (int f = 0; f < 16; f++) {
        float v = w[f];
        s = fmaf(v, __ldg(&a_s[h * 16 + f]), s);
        d = fmaf(v, __ldg(&a_d[h * 16 + f]), d);
    }
    g_es[i] = s; g_ed[i] = d;
}

__global__ void k_esed1() {
    int i = blockIdx.x * blockDim.x + threadIdx.x;
    if (i >= Nn * Hh) return;
    int n = i >> 3, h = i & 7;
    const float* x = &g_x1[n * Dd];
    const float* u = &g_u1[h * Dd];
    const float* v = &g_v1[h * Dd];
    float s = 0.f, d = 0.f;
    #pragma unroll 8
    for (int k = 0; k < Dd; k++) {
        float xv = x[k];
        s = fmaf(xv, u[k], s);
        d = fmaf(xv, v[k], d);
    }
    g_es[i] = s; g_ed[i] = d;
}

// ---------------- attention softmax: warp per dst row ----------------
// Pass 1 gathers logits ONCE and stages them in g_att (coalesced);
// passes 2-3 re-read g_att linearly (no repeated random gathers).
__global__ void k_att() {
    int wid  = (blockIdx.x * blockDim.x + threadIdx.x) >> 5;
    int lane = threadIdx.x & 31;
    if (wid >= Nn) return;
    int p0 = g_rowptr[wid], p1 = g_rowptr[wid + 1];
    int deg = p1 - p0;
    if (deg == 0) return;
    int h = lane & 7;                 // fixed per lane (stride 32 over edges)
    float edv = g_ed[wid * 8 + h];
    int tot = deg * 8;
    float m = -1e30f;
    for (int i = lane; i < tot; i += 32) {
        int e = i >> 3;
        float x = g_es[g_ssrc[p0 + e] * 8 + h] + edv;
        x = x > 0.f ? x : 0.2f * x;        // leaky relu
        g_att[(p0 + e) * 8 + h] = x;       // stage logit
        m = fmaxf(m, x);
    }
    m = fmaxf(m, __shfl_xor_sync(0xffffffffu, m, 8));
    m = fmaxf(m, __shfl_xor_sync(0xffffffffu, m, 16));
    float s = 0.f;
    for (int i = lane; i < tot; i += 32) {
        int e = i >> 3;
        s += __expf(g_att[(p0 + e) * 8 + h] - m);
    }
    s += __shfl_xor_sync(0xffffffffu, s, 8);
    s += __shfl_xor_sync(0xffffffffu, s, 16);
    float inv = 1.f / fmaxf(s, 1e-16f);
    for (int i = lane; i < tot; i += 32) {
        int e = i >> 3;
        g_att[(p0 + e) * 8 + h] = __expf(g_att[(p0 + e) * 8 + h] - m) * inv;
    }
}

// ---------------- aggregations (block per dst row, no atomics) ----------------
__global__ void k_agg_gat0() {
    int r = blockIdx.x, t = threadIdx.x;
    int p0 = g_rowptr[r], p1 = g_rowptr[r + 1];
    int h = t >> 4;
    float acc = 0.f;
    #pragma unroll 4
    for (int p = p0; p < p1; p++)
        acc = fmaf(g_att[p * 8 + h], g_Wh0[g_ssrc[p] * Dd + t], acc);
    g_x1[r * Dd + t] = acc > 0.f ? acc : expm1f(acc);   // ELU
}

__global__ void k_agg_gat1() {
    int r = blockIdx.x, t = threadIdx.x;
    int p0 = g_rowptr[r], p1 = g_rowptr[r + 1];
    float acc[8] = {0.f, 0.f, 0.f, 0.f, 0.f, 0.f, 0.f, 0.f};
    for (int p = p0; p < p1; p++) {
        float v = g_x1[g_ssrc[p] * Dd + t];
        float4 a0 = *(const float4*)&g_att[p * 8];
        float4 a1 = *(const float4*)&g_att[p * 8 + 4];
        acc[0] = fmaf(a0.x, v, acc[0]); acc[1] = fmaf(a0.y, v, acc[1]);
        acc[2] = fmaf(a0.z, v, acc[2]); acc[3] = fmaf(a0.w, v, acc[3]);
        acc[4] = fmaf(a1.x, v, acc[4]); acc[5] = fmaf(a1.y, v, acc[5]);
        acc[6] = fmaf(a1.z, v, acc[6]); acc[7] = fmaf(a1.w, v, acc[7]);
    }
    int base = r * 1024 + t;
    #pragma unroll
    for (int h = 0; h < 8; h++) g_y[base + h * Dd] = acc[h];
}

__global__ void k_agg_gcn(const float* __restrict__ hsrc, float* __restrict__ out) {
    __shared__ float red[128];
    int r = blockIdx.x, t = threadIdx.x;
    int p0 = g_rowptr[r], p1 = g_rowptr[r + 1];
    float ds = 0.f;
    for (int p = p0 + t; p < p1; p += 128) ds += g_sw[p];
    red[t] = ds;
    __syncthreads();
    for (int d = 64; d > 0; d >>= 1) {
        if (t < d) red[t] += red[t + d];
        __syncthreads();
    }
    float inv = 1.f / fmaxf(red[0], 1e-16f);
    float acc = 0.f;
    #pragma unroll 4
    for (int p = p0; p < p1; p++)
        acc = fmaf(g_sw[p] * inv, hsrc[g_ssrc[p] * Dd + t], acc);
    out[r * Dd + t] = fmaxf(acc, 0.f);                  // ReLU
}

// ---------------- SGEMM: C[M,128] = alpha * A[M,K] @ B[K,128] ----------------
__global__ __launch_bounds__(256, 2) void sgemm_k(
    const float* __restrict__ A, const float* __restrict__ B,
    float* __restrict__ C, int M, int K, float alpha)
{
    __shared__ float As[16][128];
    __shared__ float Bs[16][128];
    const int tid  = threadIdx.x;
    const int row0 = blockIdx.x * 128;

    const int ar = tid >> 2;            // 0..63
    const int ac = (tid & 3) << 2;      // 0,4,8,12
    const int br = tid >> 5;            // 0..7
    const int bc = (tid & 31) << 2;     // 0..124

    const int trow = (tid >> 4) << 3;   // 0..120
    const int tcol = (tid & 15) << 3;   // 0..120

    float acc[8][8] = {};

    for (int k0 = 0; k0 < K; k0 += 16) {
        float4 a0 = make_float4(0.f, 0.f, 0.f, 0.f), a1 = a0;
        int r0g = row0 + ar, r1g = row0 + ar + 64;
        if (r0g < M) a0 = *(const float4*)&A[(size_t)r0g * K + k0 + ac];
        if (r1g < M) a1 = *(const float4*)&A[(size_t)r1g * K + k0 + ac];
        float4 b0 = *(const float4*)&B[(size_t)(k0 + br) * 128 + bc];
        float4 b1 = *(const float4*)&B[(size_t)(k0 + br + 8) * 128 + bc];
        __syncthreads();
        As[ac + 0][ar] = a0.x; As[ac + 1][ar] = a0.y;
        As[ac + 2][ar] = a0.z; As[ac + 3][ar] = a0.w;
        As[ac + 0][ar + 64] = a1.x; As[ac + 1][ar + 64] = a1.y;
        As[ac + 2][ar + 64] = a1.z; As[ac + 3][ar + 64] = a1.w;
        *(float4*)&Bs[br][bc]     = b0;
        *(float4*)&Bs[br + 8][bc] = b1;
        __syncthreads();
        #pragma unroll
        for (int kk = 0; kk < 16; kk++) {
            float ra[8], rb[8];
            *(float4*)(ra)     = *(const float4*)&As[kk][trow];
            *(float4*)(ra + 4) = *(const float4*)&As[kk][trow + 4];
            *(float4*)(rb)     = *(const float4*)&Bs[kk][tcol];
            *(float4*)(rb + 4) = *(const float4*)&Bs[kk][tcol + 4];
            #pragma unroll
            for (int i = 0; i < 8; i++)
                #pragma unroll
                for (int j = 0; j < 8; j++)
                    acc[i][j] = fmaf(ra[i], rb[j], acc[i][j]);
        }
    }
    #pragma unroll
    for (int i = 0; i < 8; i++) {
        int r = row0 + trow + i;
        if (r < M) {
            float4 v0 = make_float4(alpha * acc[i][0], alpha * acc[i][1],
                                    alpha * acc[i][2], alpha * acc[i][3]);
            float4 v1 = make_float4(alpha * acc[i][4], alpha * acc[i][5],
                                    alpha * acc[i][6], alpha * acc[i][7]);
            *(float4*)&C[(size_t)r * 128 + tcol]     = v0;
            *(float4*)&C[(size_t)r * 128 + tcol + 4] = v1;
        }
    }
}

// ---------------- final elementwise max ----------------
__global__ void k_final(float* __restrict__ out) {
    int i = blockIdx.x * blockDim.x + threadIdx.x;
    if (i < Nn * Dd) out[i] = fmaxf(out[i], g_x2b[i]);
}

// ---------------- launch ----------------
extern "C" void kernel_launch(void* const* d_in, const int* in_sizes, int n_in,
                              void* d_out, int out_size) {
    const float* x   = (const float*)d_in[0];
    const int*   ei  = (const int*)d_in[1];     // int32 OR int64 bits; normalized on device
    const float* ew  = (const float*)d_in[2];
    const float* W0  = (const float*)d_in[3];
    const float* a0s = (const float*)d_in[4];
    const float* a0d = (const float*)d_in[5];
    const float* W1  = (const float*)d_in[6];
    const float* a1s = (const float*)d_in[7];
    const float* a1d = (const float*)d_in[8];
    const float* gW0 = (const float*)d_in[9];
    const float* gW1 = (const float*)d_in[10];
    float* out = (float*)d_out;

    float *pW0p, *pWh0, *pY, *pHg, *pX2, *pX2b;
    cudaGetSymbolAddress((void**)&pW0p, g_W0p);
    cudaGetSymbolAddress((void**)&pWh0, g_Wh0);
    cudaGetSymbolAddress((void**)&pY,   g_y);
    cudaGetSymbolAddress((void**)&pHg,  g_hg);
    cudaGetSymbolAddress((void**)&pX2,  g_x2);
    cudaGetSymbolAddress((void**)&pX2b, g_x2b);

    const int gA = (Nn + 127) / 128;

    // edge-index normalization + CSR build (sorted-by-dst edges)
    k_detect <<<1, 32>>>(ei);
    k_convert<<<(2 * Ee + 255) / 256, 256>>>(ei);
    k_zero   <<<(Nn + 255) / 256, 256>>>();
    k_count  <<<(Ee + 255) / 256, 256>>>();
    k_scan   <<<1, 1024>>>();
    k_scatter<<<(Ee + 255) / 256, 256>>>(ew);

    // GAT layer 0
    k_packW0 <<<(Dd * Dd + 255) / 256, 256>>>(W0);
    sgemm_k  <<<gA, 256>>>(x, pW0p, pWh0, Nn, 128, 1.f);
    k_esed0  <<<(Nn * Hh + 255) / 256, 256>>>(a0s, a0d);
    k_att    <<<(Nn + 7) / 8, 256>>>();
    k_agg_gat0<<<Nn, 128>>>();

    // GCN layer 0
    sgemm_k  <<<gA, 256>>>(x, gW0, pHg, Nn, 128, 1.f);
    k_agg_gcn<<<Nn, 128>>>(pHg, pX2);

    // GAT layer 1 (linearity trick: aggregate x1 per head, then one big GEMM)
    k_uv1    <<<4, 256>>>(W1, a1s, a1d);
    k_esed1  <<<(Nn * Hh + 255) / 256, 256>>>();
    k_att    <<<(Nn + 7) / 8, 256>>>();
    k_agg_gat1<<<Nn, 128>>>();
    sgemm_k  <<<gA, 256>>>(pY, W1, out, Nn, 1024, 0.125f);   // mean over 8 heads

    // GCN layer 1
    sgemm_k  <<<gA, 256>>>(pX2, gW1, pHg, Nn, 128, 1.f);
    k_agg_gcn<<<Nn, 128>>>(pHg, pX2b);

    // final: max(gat, gcn)
    k_final  <<<(Nn * Dd + 255) / 256, 256>>>(out);
}

// round 11
// speedup vs baseline: 1.2228x; 1.2228x over previous
#include <cuda_runtime.h>
#include <cuda_bf16.h>
#include <math.h>

#define Nn 50000
#define Ee 800000
#define Hh 8
#define Dd 128

// ---------------- scratch (static device globals; no runtime alloc) ----------------
__device__ int   g_is64;
__device__ int   g_eidx[2 * Ee];
__device__ int   g_rowcnt[Nn];
__device__ int   g_cursor[Nn];
__device__ int   g_rowptr[Nn + 1];
__device__ int   g_ssrc[Ee];
__device__ float g_sw[Ee];
__device__ float g_W0p[Dd * Dd];
__device__ float g_Wh0[Nn * Dd];
__device__ float g_es[Nn * Hh];
__device__ float g_ed[Nn * Hh];
__device__ float g_att[Ee * Hh];
__device__ float g_x1[Nn * Dd];                 // GAT layer-0 output (post-ELU)
__device__ __nv_bfloat16 g_yh[Nn * 1024];       // split-bf16 aggregated x1 (hi)
__device__ __nv_bfloat16 g_yl[Nn * 1024];       // split-bf16 aggregated x1 (lo)
__device__ __nv_bfloat16 g_Bth[128 * 1024];     // W1 packed [n][k], hi
__device__ __nv_bfloat16 g_Btl[128 * 1024];     // W1 packed [n][k], lo
__device__ float g_hg[Nn * Dd];
__device__ float g_x2[Nn * Dd];
__device__ float g_x2b[Nn * Dd];
__device__ float g_u1[Hh * Dd];
__device__ float g_v1[Hh * Dd];

// ---------------- base-target PTX helpers (sm_80+ features only) ----------------
__device__ __forceinline__ unsigned s2u(const void* p) {
    unsigned a;
    asm("{ .reg .u64 t; cvta.to.shared.u64 t, %1; cvt.u32.u64 %0, t; }" : "=r"(a) : "l"(p));
    return a;
}
__device__ __forceinline__ void cpa16(unsigned dst, const void* src, int szsrc) {
    asm volatile("cp.async.cg.shared.global [%0], [%1], 16, %2;"
                 :: "r"(dst), "l"(src), "r"(szsrc) : "memory");
}
__device__ __forceinline__ void cpa_commit() {
    asm volatile("cp.async.commit_group;" ::: "memory");
}
template <int N>
__device__ __forceinline__ void cpa_wait() {
    asm volatile("cp.async.wait_group %0;" :: "n"(N) : "memory");
}
__device__ __forceinline__ void ldmx4(unsigned* r, unsigned addr) {
    asm volatile("ldmatrix.sync.aligned.m8n8.x4.shared.b16 {%0,%1,%2,%3}, [%4];"
                 : "=r"(r[0]), "=r"(r[1]), "=r"(r[2]), "=r"(r[3]) : "r"(addr));
}
__device__ __forceinline__ void ldmx2(unsigned* r, unsigned addr) {
    asm volatile("ldmatrix.sync.aligned.m8n8.x2.shared.b16 {%0,%1}, [%2];"
                 : "=r"(r[0]), "=r"(r[1]) : "r"(addr));
}
__device__ __forceinline__ void mma16816(float* c, const unsigned* a, const unsigned* b) {
    asm volatile(
        "mma.sync.aligned.m16n8k16.row.col.f32.bf16.bf16.f32 "
        "{%0,%1,%2,%3}, {%4,%5,%6,%7}, {%8,%9}, {%0,%1,%2,%3};"
        : "+f"(c[0]), "+f"(c[1]), "+f"(c[2]), "+f"(c[3])
        : "r"(a[0]), "r"(a[1]), "r"(a[2]), "r"(a[3]), "r"(b[0]), "r"(b[1]));
}

// ---------------- edge-index dtype detection + normalization ----------------
__global__ void k_detect(const int* __restrict__ ei32) {
    if (threadIdx.x == 0 && blockIdx.x == 0) {
        int is64 = 1;
        for (int i = 0; i < 256; i++)
            if (ei32[2 * i + 1] != 0) { is64 = 0; break; }
        g_is64 = is64;
    }
}
__global__ void k_convert(const int* __restrict__ ei32) {
    int i = blockIdx.x * blockDim.x + threadIdx.x;
    if (i >= 2 * Ee) return;
    g_eidx[i] = g_is64 ? ei32[2 * i] : ei32[i];
}

// ---------------- CSR build ----------------
__global__ void k_zero() {
    int i = blockIdx.x * blockDim.x + threadIdx.x;
    if (i < Nn) { g_rowcnt[i] = 0; g_cursor[i] = 0; }
}
__global__ void k_count() {
    int i = blockIdx.x * blockDim.x + threadIdx.x;
    if (i < Ee) atomicAdd(&g_rowcnt[g_eidx[Ee + i]], 1);
}
__global__ void k_scan() {
    __shared__ int tmp[1024];
    __shared__ int s_off;
    int t = threadIdx.x;
    if (t == 0) { s_off = 0; g_rowptr[0] = 0; }
    __syncthreads();
    for (int base = 0; base < Nn; base += 1024) {
        int i = base + t;
        int v = (i < Nn) ? g_rowcnt[i] : 0;
        tmp[t] = v;
        __syncthreads();
        for (int d = 1; d < 1024; d <<= 1) {
            int add = (t >= d) ? tmp[t - d] : 0;
            __syncthreads();
            tmp[t] += add;
            __syncthreads();
        }
        if (i < Nn) g_rowptr[i + 1] = s_off + tmp[t];
        __syncthreads();
        if (t == 1023) s_off += tmp[1023];
        __syncthreads();
    }
}
__global__ void k_scatter(const float* __restrict__ w) {
    int i = blockIdx.x * blockDim.x + threadIdx.x;
    if (i >= Ee) return;
    int s = g_eidx[i];
    int d = g_eidx[Ee + i];
    int p = g_rowptr[d] + atomicAdd(&g_cursor[d], 1);
    g_ssrc[p] = s;
    g_sw[p]   = w[i];
}

// ---------------- weight prep ----------------
__global__ void k_packW0(const float* __restrict__ W0) {
    int i = blockIdx.x * blockDim.x + threadIdx.x;
    if (i >= Dd * Dd) return;
    int k = i >> 7, c = i & 127;
    int h = c >> 4, f = c & 15;
    g_W0p[k * Dd + c] = W0[h * (Dd * 16) + k * 16 + f];
}
// W1 [8][128][128] -> Bt[n][k] (k = h*128 + kk), split bf16 hi/lo
__global__ void k_packW1(const float* __restrict__ W1) {
    int i = blockIdx.x * blockDim.x + threadIdx.x;
    if (i >= 128 * 1024) return;
    int n = i >> 10, k = i & 1023;
    int h = k >> 7, kk = k & 127;
    float w = W1[h * (Dd * Dd) + kk * Dd + n];
    __nv_bfloat16 hi = __float2bfloat16(w);
    __nv_bfloat16 lo = __float2bfloat16(w - __bfloat162float(hi));
    g_Bth[i] = hi; g_Btl[i] = lo;
}
__global__ void k_uv1(const float* __restrict__ W1,
                      const float* __restrict__ a_s, const float* __restrict__ a_d) {
    int i = blockIdx.x * blockDim.x + threadIdx.x;
    if (i >= Hh * Dd) return;
    int h = i >> 7, k = i & 127;
    const float* w = &W1[h * Dd * Dd + k * Dd];
    float su = 0.f, sv = 0.f;
    #pragma unroll 8
    for (int f = 0; f < Dd; f++) {
        float v = __ldg(&w[f]);
        su = fmaf(v, __ldg(&a_s[h * Dd + f]), su);
        sv = fmaf(v, __ldg(&a_d[h * Dd + f]), sv);
    }
    g_u1[i] = su; g_v1[i] = sv;
}

// ---------------- es / ed ----------------
__global__ void k_esed0(const float* __restrict__ a_s, const float* __restrict__ a_d) {
    int i = blockIdx.x * blockDim.x + threadIdx.x;
    if (i >= Nn * Hh) return;
    int n = i >> 3, h = i & 7;
    const float* w = &g_Wh0[n * Dd + h * 16];
    float s = 0.f, d = 0.f;
    #pragma unroll
    for (int f = 0; f < 16; f++) {
        float v = w[f];
        s = fmaf(v, __ldg(&a_s[h * 16 + f]), s);
        d = fmaf(v, __ldg(&a_d[h * 16 + f]), d);
    }
    g_es[i] = s; g_ed[i] = d;
}
__global__ void k_esed1() {
    int i = blockIdx.x * blockDim.x + threadIdx.x;
    if (i >= Nn * Hh) return;
    int n = i >> 3, h = i & 7;
    const float* x = &g_x1[n * Dd];
    const float* u = &g_u1[h * Dd];
    const float* v = &g_v1[h * Dd];
    float s = 0.f, d = 0.f;
    #pragma unroll 8
    for (int k = 0; k < Dd; k++) {
        float xv = x[k];
        s = fmaf(xv, u[k], s);
        d = fmaf(xv, v[k], d);
    }
    g_es[i] = s; g_ed[i] = d;
}

// ---------------- attention softmax: warp per dst row ----------------
__global__ void k_att() {
    int wid  = (blockIdx.x * blockDim.x + threadIdx.x) >> 5;
    int lane = threadIdx.x & 31;
    if (wid >= Nn) return;
    int p0 = g_rowptr[wid], p1 = g_rowptr[wid + 1];
    int deg = p1 - p0;
    if (deg == 0) return;
    int h = lane & 7;
    float edv = g_ed[wid * 8 + h];
    int tot = deg * 8;
    float m = -1e30f;
    for (int i = lane; i < tot; i += 32) {
        int e = i >> 3;
        float x = g_es[g_ssrc[p0 + e] * 8 + h] + edv;
        x = x > 0.f ? x : 0.2f * x;
        g_att[(p0 + e) * 8 + h] = x;
        m = fmaxf(m, x);
    }
    m = fmaxf(m, __shfl_xor_sync(0xffffffffu, m, 8));
    m = fmaxf(m, __shfl_xor_sync(0xffffffffu, m, 16));
    float s = 0.f;
    for (int i = lane; i < tot; i += 32) {
        int e = i >> 3;
        s += __expf(g_att[(p0 + e) * 8 + h] - m);
    }
    s += __shfl_xor_sync(0xffffffffu, s, 8);
    s += __shfl_xor_sync(0xffffffffu, s, 16);
    float inv = 1.f / fmaxf(s, 1e-16f);
    for (int i = lane; i < tot; i += 32) {
        int e = i >> 3;
        g_att[(p0 + e) * 8 + h] = __expf(g_att[(p0 + e) * 8 + h] - m) * inv;
    }
}

// ---------------- aggregations (block per dst row, no atomics) ----------------
__global__ void k_agg_gat0() {
    int r = blockIdx.x, t = threadIdx.x;
    int p0 = g_rowptr[r], p1 = g_rowptr[r + 1];
    int h = t >> 4;
    float acc = 0.f;
    #pragma unroll 4
    for (int p = p0; p < p1; p++)
        acc = fmaf(g_att[p * 8 + h], g_Wh0[g_ssrc[p] * Dd + t], acc);
    g_x1[r * Dd + t] = acc > 0.f ? acc : expm1f(acc);
}
__global__ void k_agg_gat1() {
    int r = blockIdx.x, t = threadIdx.x;
    int p0 = g_rowptr[r], p1 = g_rowptr[r + 1];
    float acc[8] = {0.f, 0.f, 0.f, 0.f, 0.f, 0.f, 0.f, 0.f};
    for (int p = p0; p < p1; p++) {
        float v = g_x1[g_ssrc[p] * Dd + t];
        float4 a0 = *(const float4*)&g_att[p * 8];
        float4 a1 = *(const float4*)&g_att[p * 8 + 4];
        acc[0] = fmaf(a0.x, v, acc[0]); acc[1] = fmaf(a0.y, v, acc[1]);
        acc[2] = fmaf(a0.z, v, acc[2]); acc[3] = fmaf(a0.w, v, acc[3]);
        acc[4] = fmaf(a1.x, v, acc[4]); acc[5] = fmaf(a1.y, v, acc[5]);
        acc[6] = fmaf(a1.z, v, acc[6]); acc[7] = fmaf(a1.w, v, acc[7]);
    }
    int base = r * 1024 + t;
    #pragma unroll
    for (int h = 0; h < 8; h++) {
        float v = acc[h];
        __nv_bfloat16 hi = __float2bfloat16(v);
        __nv_bfloat16 lo = __float2bfloat16(v - __bfloat162float(hi));
        g_yh[base + h * Dd] = hi;
        g_yl[base + h * Dd] = lo;
    }
}
__global__ void k_agg_gcn(const float* __restrict__ hsrc, float* __restrict__ out) {
    __shared__ float red[128];
    int r = blockIdx.x, t = threadIdx.x;
    int p0 = g_rowptr[r], p1 = g_rowptr[r + 1];
    float ds = 0.f;
    for (int p = p0 + t; p < p1; p += 128) ds += g_sw[p];
    red[t] = ds;
    __syncthreads();
    for (int d = 64; d > 0; d >>= 1) {
        if (t < d) red[t] += red[t + d];
        __syncthreads();
    }
    float inv = 1.f / fmaxf(red[0], 1e-16f);
    float acc = 0.f;
    #pragma unroll 4
    for (int p = p0; p < p1; p++)
        acc = fmaf(g_sw[p] * inv, hsrc[g_ssrc[p] * Dd + t], acc);
    out[r * Dd + t] = fmaxf(acc, 0.f);
}

// ---------------- fp32 SGEMM (small GEMMs): C[M,128] = A[M,K] @ B[K,128] ----------------
__global__ __launch_bounds__(256, 2) void sgemm_k(
    const float* __restrict__ A, const float* __restrict__ B,
    float* __restrict__ C, int M, int K, float alpha)
{
    __shared__ float As[16][128];
    __shared__ float Bs[16][128];
    const int tid  = threadIdx.x;
    const int row0 = blockIdx.x * 128;
    const int ar = tid >> 2;
    const int ac = (tid & 3) << 2;
    const int br = tid >> 5;
    const int bc = (tid & 31) << 2;
    const int trow = (tid >> 4) << 3;
    const int tcol = (tid & 15) << 3;
    float acc[8][8] = {};
    for (int k0 = 0; k0 < K; k0 += 16) {
        float4 a0 = make_float4(0.f, 0.f, 0.f, 0.f), a1 = a0;
        int r0g = row0 + ar, r1g = row0 + ar + 64;
        if (r0g < M) a0 = *(const float4*)&A[(size_t)r0g * K + k0 + ac];
        if (r1g < M) a1 = *(const float4*)&A[(size_t)r1g * K + k0 + ac];
        float4 b0 = *(const float4*)&B[(size_t)(k0 + br) * 128 + bc];
        float4 b1 = *(const float4*)&B[(size_t)(k0 + br + 8) * 128 + bc];
        __syncthreads();
        As[ac + 0][ar] = a0.x; As[ac + 1][ar] = a0.y;
        As[ac + 2][ar] = a0.z; As[ac + 3][ar] = a0.w;
        As[ac + 0][ar + 64] = a1.x; As[ac + 1][ar + 64] = a1.y;
        As[ac + 2][ar + 64] = a1.z; As[ac + 3][ar + 64] = a1.w;
        *(float4*)&Bs[br][bc]     = b0;
        *(float4*)&Bs[br + 8][bc] = b1;
        __syncthreads();
        #pragma unroll
        for (int kk = 0; kk < 16; kk++) {
            float ra[8], rb[8];
            *(float4*)(ra)     = *(const float4*)&As[kk][trow];
            *(float4*)(ra + 4) = *(const float4*)&As[kk][trow + 4];
            *(float4*)(rb)     = *(const float4*)&Bs[kk][tcol];
            *(float4*)(rb + 4) = *(const float4*)&Bs[kk][tcol + 4];
            #pragma unroll
            for (int i = 0; i < 8; i++)
                #pragma unroll
                for (int j = 0; j < 8; j++)
                    acc[i][j] = fmaf(ra[i], rb[j], acc[i][j]);
        }
    }
    #pragma unroll
    for (int i = 0; i < 8; i++) {
        int r = row0 + trow + i;
        if (r < M) {
            float4 v0 = make_float4(alpha * acc[i][0], alpha * acc[i][1],
                                    alpha * acc[i][2], alpha * acc[i][3]);
            float4 v1 = make_float4(alpha * acc[i][4], alpha * acc[i][5],
                                    alpha * acc[i][6], alpha * acc[i][7]);
            *(float4*)&C[(size_t)r * 128 + tcol]     = v0;
            *(float4*)&C[(size_t)r * 128 + tcol + 4] = v1;
        }
    }
}

// ---------------- mma.sync split-bf16 GEMM: C[M,128] = alpha * y @ Bt^T ----------------
// A = (yh|yl)[M,1024] bf16 K-major; B = (Bth|Btl)[128,1024] bf16 K-major.
// 3 passes: hi*hi + hi*lo + lo*hi (lo*lo ~2^-16, dropped). fp32 accumulate.
// Block: 128x128 tile, 8 warps in 2(m) x 4(n) grid, warp tile 64x32 (4x4 m16n8k16).
// K staged in 64-wide chunks, cp.async double-buffered; SMEM pitch 144B (ldmatrix-friendly).
#define TCH 64
#define NCH 16
#define PITCHB 144                       // 72 bf16 per row
#define TILE_BYTES (128 * PITCHB)        // 18432
#define BUF_BYTES (4 * TILE_BYTES)       // Ah, Al, Bh, Bl

extern "C" __global__ __launch_bounds__(256, 1) void gemm_tc(
    const __nv_bfloat16* __restrict__ Ah, const __nv_bfloat16* __restrict__ Al,
    float* __restrict__ C, float alpha, int M)
{
    extern __shared__ char smem[];
    const unsigned sbase = s2u(smem);
    const int tid  = threadIdx.x;
    const int wid  = tid >> 5;
    const int lane = tid & 31;
    const int row0 = blockIdx.x * 128;
    const int mw = wid & 1, nw = wid >> 1;
    const int m0 = mw * 64, n0 = nw * 32;

    const __nv_bfloat16* srcs[4] = { Ah, Al, g_Bth, g_Btl };

    // ---- chunk loader: 4096 16B cp.asyncs per chunk, 16 per thread ----
    auto load_chunk = [&](int c, int buf) {
        unsigned bb = sbase + buf * BUF_BYTES;
        #pragma unroll
        for (int i = 0; i < 16; i++) {
            int o   = tid + 256 * i;
            int tl  = o >> 10;           // 0..3: Ah, Al, Bh, Bl
            int r   = (o & 1023) >> 3;   // row 0..127
            int seg = o & 7;             // 16B segment
            unsigned dst = bb + tl * TILE_BYTES + r * PITCHB + seg * 16;
            size_t goff = (size_t)c * TCH + seg * 8;
            const __nv_bfloat16* s;
            int ok = 16;
            if (tl < 2) {
                int gr = row0 + r;
                s = srcs[tl] + (size_t)gr * 1024 + goff;
                if (gr >= M) ok = 0;     // zero-fill out-of-range rows
            } else {
                s = srcs[tl] + (size_t)r * 1024 + goff;
            }
            cpa16(dst, s, ok);
        }
        cpa_commit();
    };

    float acc[4][4][4] = {};

    load_chunk(0, 0);

    for (int c = 0; c < NCH; c++) {
        int buf = c & 1;
        if (c + 1 < NCH) { load_chunk(c + 1, buf ^ 1); cpa_wait<1>(); }
        else             { cpa_wait<0>(); }
        __syncthreads();

        unsigned bb  = sbase + buf * BUF_BYTES;
        unsigned uAh = bb;
        unsigned uAl = bb + TILE_BYTES;
        unsigned uBh = bb + 2 * TILE_BYTES;
        unsigned uBl = bb + 3 * TILE_BYTES;

        int l15 = lane & 15;
        #pragma unroll
        for (int ks = 0; ks < 4; ks++) {
            unsigned ah[4][4], al[4][4], bh[4][2], bl[4][2];
            unsigned aoff = (unsigned)(m0 + l15) * PITCHB + ks * 32 + (lane >> 4) * 16;
            #pragma unroll
            for (int i = 0; i < 4; i++) {
                ldmx4(ah[i], uAh + aoff + i * 16 * PITCHB);
                ldmx4(al[i], uAl + aoff + i * 16 * PITCHB);
            }
            unsigned boff = (unsigned)(n0 + (l15 & 7)) * PITCHB + ks * 32 + (l15 >> 3) * 16;
            #pragma unroll
            for (int j = 0; j < 4; j++) {
                ldmx2(bh[j], uBh + boff + j * 8 * PITCHB);
                ldmx2(bl[j], uBl + boff + j * 8 * PITCHB);
            }
            #pragma unroll
            for (int i = 0; i < 4; i++)
                #pragma unroll
                for (int j = 0; j < 4; j++) {
                    mma16816(acc[i][j], ah[i], bh[j]);
                    mma16816(acc[i][j], ah[i], bl[j]);
                    mma16816(acc[i][j], al[i], bh[j]);
                }
        }
        __syncthreads();
    }

    // ---- epilogue: C fragment (c0,c1)@(row, col), (c2,c3)@(row+8, col) ----
    int rb = row0 + m0 + (lane >> 2);
    int cb = n0 + (lane & 3) * 2;
    #pragma unroll
    for (int i = 0; i < 4; i++) {
        #pragma unroll
        for (int j = 0; j < 4; j++) {
            int r1 = rb + i * 16, c1 = cb + j * 8;
            if (r1 < M)
                *(float2*)&C[(size_t)r1 * 128 + c1] =
                    make_float2(acc[i][j][0] * alpha, acc[i][j][1] * alpha);
            int r2 = r1 + 8;
            if (r2 < M)
                *(float2*)&C[(size_t)r2 * 128 + c1] =
                    make_float2(acc[i][j][2] * alpha, acc[i][j][3] * alpha);
        }
    }
}

// ---------------- final elementwise max ----------------
__global__ void k_final(float* __restrict__ out) {
    int i = blockIdx.x * blockDim.x + threadIdx.x;
    if (i < Nn * Dd) out[i] = fmaxf(out[i], g_x2b[i]);
}

// ---------------- launch ----------------
extern "C" void kernel_launch(void* const* d_in, const int* in_sizes, int n_in,
                              void* d_out, int out_size) {
    const float* x   = (const float*)d_in[0];
    const int*   ei  = (const int*)d_in[1];
    const float* ew  = (const float*)d_in[2];
    const float* W0  = (const float*)d_in[3];
    const float* a0s = (const float*)d_in[4];
    const float* a0d = (const float*)d_in[5];
    const float* W1  = (const float*)d_in[6];
    const float* a1s = (const float*)d_in[7];
    const float* a1d = (const float*)d_in[8];
    const float* gW0 = (const float*)d_in[9];
    const float* gW1 = (const float*)d_in[10];
    float* out = (float*)d_out;

    float *pW0p, *pWh0, *pHg, *pX2, *pX2b;
    __nv_bfloat16 *pYh, *pYl;
    cudaGetSymbolAddress((void**)&pW0p, g_W0p);
    cudaGetSymbolAddress((void**)&pWh0, g_Wh0);
    cudaGetSymbolAddress((void**)&pYh,  g_yh);
    cudaGetSymbolAddress((void**)&pYl,  g_yl);
    cudaGetSymbolAddress((void**)&pHg,  g_hg);
    cudaGetSymbolAddress((void**)&pX2,  g_x2);
    cudaGetSymbolAddress((void**)&pX2b, g_x2b);

    const int gA = (Nn + 127) / 128;
    const int SMEM_TC = 2 * BUF_BYTES;   // 147456 bytes
    cudaFuncSetAttribute(gemm_tc, cudaFuncAttributeMaxDynamicSharedMemorySize, SMEM_TC);

    // edge-index normalization + CSR build
    k_detect <<<1, 32>>>(ei);
    k_convert<<<(2 * Ee + 255) / 256, 256>>>(ei);
    k_zero   <<<(Nn + 255) / 256, 256>>>();
    k_count  <<<(Ee + 255) / 256, 256>>>();
    k_scan   <<<1, 1024>>>();
    k_scatter<<<(Ee + 255) / 256, 256>>>(ew);

    // GAT layer 0
    k_packW0 <<<(Dd * Dd + 255) / 256, 256>>>(W0);
    sgemm_k  <<<gA, 256>>>(x, pW0p, pWh0, Nn, 128, 1.f);
    k_esed0  <<<(Nn * Hh + 255) / 256, 256>>>(a0s, a0d);
    k_att    <<<(Nn + 7) / 8, 256>>>();
    k_agg_gat0<<<Nn, 128>>>();

    // GCN layer 0
    sgemm_k  <<<gA, 256>>>(x, gW0, pHg, Nn, 128, 1.f);
    k_agg_gcn<<<Nn, 128>>>(pHg, pX2);

    // GAT layer 1: aggregate (split-bf16) then one tensor-core GEMM
    k_packW1 <<<(128 * 1024 + 255) / 256, 256>>>(W1);
    k_uv1    <<<4, 256>>>(W1, a1s, a1d);
    k_esed1  <<<(Nn * Hh + 255) / 256, 256>>>();
    k_att    <<<(Nn + 7) / 8, 256>>>();
    k_agg_gat1<<<Nn, 128>>>();
    gemm_tc  <<<gA, 256, SMEM_TC>>>(pYh, pYl, out, 0.125f, Nn);

    // GCN layer 1
    sgemm_k  <<<gA, 256>>>(pX2, gW1, pHg, Nn, 128, 1.f);
    k_agg_gcn<<<Nn, 128>>>(pHg, pX2b);

    // final: max(gat, gcn)
    k_final  <<<(Nn * Dd + 255) / 256, 256>>>(out);
}

// round 14
// speedup vs baseline: 1.3010x; 1.0639x over previous
#include <cuda_runtime.h>
#include <cuda_bf16.h>
#include <math.h>

#define Nn 50000
#define Ee 800000
#define Hh 8
#define Dd 128

// ---------------- scratch (static device globals; no runtime alloc) ----------------
__device__ int   g_is64;
__device__ int   g_eidx[2 * Ee];
__device__ int   g_rowcnt[Nn];
__device__ int   g_cursor[Nn];
__device__ int   g_rowptr[Nn + 1];
__device__ int   g_ssrc[Ee];
__device__ float g_sw[Ee];
__device__ float g_Wh0[Nn * Dd];
__device__ float g_es[Nn * Hh];
__device__ float g_ed[Nn * Hh];
__device__ float g_att[Ee * Hh];
__device__ float g_x1[Nn * Dd];                 // GAT layer-0 output (post-ELU)
__device__ __nv_bfloat16 g_xh[Nn * Dd];         // split input x (hi/lo)
__device__ __nv_bfloat16 g_xl[Nn * Dd];
__device__ __nv_bfloat16 g_x2h[Nn * Dd];        // split GCN layer-1 output
__device__ __nv_bfloat16 g_x2l[Nn * Dd];
__device__ __nv_bfloat16 g_yh[Nn * 1024];       // split aggregated x1 (per head)
__device__ __nv_bfloat16 g_yl[Nn * 1024];
__device__ __nv_bfloat16 g_Bth[128 * 1024];     // W1 packed [n][k]
__device__ __nv_bfloat16 g_Btl[128 * 1024];
__device__ __nv_bfloat16 g_B0h[128 * 128];      // W0 packed [n][k]
__device__ __nv_bfloat16 g_B0l[128 * 128];
__device__ __nv_bfloat16 g_Bg0h[128 * 128];     // gcn_W0 packed [n][k]
__device__ __nv_bfloat16 g_Bg0l[128 * 128];
__device__ __nv_bfloat16 g_Bg1h[128 * 128];     // gcn_W1 packed [n][k]
__device__ __nv_bfloat16 g_Bg1l[128 * 128];
__device__ float g_hg[Nn * Dd];
__device__ float g_x2b[Nn * Dd];
__device__ float g_u1[Hh * Dd];
__device__ float g_v1[Hh * Dd];

// ---------------- base-target PTX helpers (sm_80+ features only) ----------------
__device__ __forceinline__ unsigned s2u(const void* p) {
    unsigned a;
    asm("{ .reg .u64 t; cvta.to.shared.u64 t, %1; cvt.u32.u64 %0, t; }" : "=r"(a) : "l"(p));
    return a;
}
__device__ __forceinline__ void cpa16(unsigned dst, const void* src, int szsrc) {
    asm volatile("cp.async.cg.shared.global [%0], [%1], 16, %2;"
                 :: "r"(dst), "l"(src), "r"(szsrc) : "memory");
}
__device__ __forceinline__ void cpa_commit() {
    asm volatile("cp.async.commit_group;" ::: "memory");
}
template <int N>
__device__ __forceinline__ void cpa_wait() {
    asm volatile("cp.async.wait_group %0;" :: "n"(N) : "memory");
}
__device__ __forceinline__ void ldmx4(unsigned* r, unsigned addr) {
    asm volatile("ldmatrix.sync.aligned.m8n8.x4.shared.b16 {%0,%1,%2,%3}, [%4];"
                 : "=r"(r[0]), "=r"(r[1]), "=r"(r[2]), "=r"(r[3]) : "r"(addr));
}
__device__ __forceinline__ void ldmx2(unsigned* r, unsigned addr) {
    asm volatile("ldmatrix.sync.aligned.m8n8.x2.shared.b16 {%0,%1}, [%2];"
                 : "=r"(r[0]), "=r"(r[1]) : "r"(addr));
}
__device__ __forceinline__ void mma16816(float* c, const unsigned* a, const unsigned* b) {
    asm volatile(
        "mma.sync.aligned.m16n8k16.row.col.f32.bf16.bf16.f32 "
        "{%0,%1,%2,%3}, {%4,%5,%6,%7}, {%8,%9}, {%0,%1,%2,%3};"
        : "+f"(c[0]), "+f"(c[1]), "+f"(c[2]), "+f"(c[3])
        : "r"(a[0]), "r"(a[1]), "r"(a[2]), "r"(a[3]), "r"(b[0]), "r"(b[1]));
}
__device__ __forceinline__ void bsplit(float v, __nv_bfloat16& hi, __nv_bfloat16& lo) {
    hi = __float2bfloat16(v);
    lo = __float2bfloat16(v - __bfloat162float(hi));
}

// ---------------- edge-index dtype detection + normalization ----------------
__global__ void k_detect(const int* __restrict__ ei32) {
    if (threadIdx.x == 0 && blockIdx.x == 0) {
        int is64 = 1;
        for (int i = 0; i < 256; i++)
            if (ei32[2 * i + 1] != 0) { is64 = 0; break; }
        g_is64 = is64;
    }
}
__global__ void k_convert(const int* __restrict__ ei32) {
    int i = blockIdx.x * blockDim.x + threadIdx.x;
    if (i >= 2 * Ee) return;
    g_eidx[i] = g_is64 ? ei32[2 * i] : ei32[i];
}

// ---------------- CSR build ----------------
__global__ void k_zero() {
    int i = blockIdx.x * blockDim.x + threadIdx.x;
    if (i < Nn) { g_rowcnt[i] = 0; g_cursor[i] = 0; }
}
__global__ void k_count() {
    int i = blockIdx.x * blockDim.x + threadIdx.x;
    if (i < Ee) atomicAdd(&g_rowcnt[g_eidx[Ee + i]], 1);
}
__global__ void k_scan() {
    __shared__ int tmp[1024];
    __shared__ int s_off;
    int t = threadIdx.x;
    if (t == 0) { s_off = 0; g_rowptr[0] = 0; }
    __syncthreads();
    for (int base = 0; base < Nn; base += 1024) {
        int i = base + t;
        int v = (i < Nn) ? g_rowcnt[i] : 0;
        tmp[t] = v;
        __syncthreads();
        for (int d = 1; d < 1024; d <<= 1) {
            int add = (t >= d) ? tmp[t - d] : 0;
            __syncthreads();
            tmp[t] += add;
            __syncthreads();
        }
        if (i < Nn) g_rowptr[i + 1] = s_off + tmp[t];
        __syncthreads();
        if (t == 1023) s_off += tmp[1023];
        __syncthreads();
    }
}
__global__ void k_scatter(const float* __restrict__ w) {
    int i = blockIdx.x * blockDim.x + threadIdx.x;
    if (i >= Ee) return;
    int s = g_eidx[i];
    int d = g_eidx[Ee + i];
    int p = g_rowptr[d] + atomicAdd(&g_cursor[d], 1);
    g_ssrc[p] = s;
    g_sw[p]   = w[i];
}

// ---------------- input split + weight packs ----------------
__global__ void k_splitx(const float* __restrict__ x) {
    int i = blockIdx.x * blockDim.x + threadIdx.x;
    if (i >= Nn * Dd) return;
    bsplit(x[i], g_xh[i], g_xl[i]);
}
// B[n][k] = W[k*128 + n], split (for gcn_W0 / gcn_W1)
__global__ void k_packWsplit(const float* __restrict__ W,
                             __nv_bfloat16* __restrict__ Bh, __nv_bfloat16* __restrict__ Bl) {
    int i = blockIdx.x * blockDim.x + threadIdx.x;
    if (i >= 128 * 128) return;
    int n = i >> 7, k = i & 127;
    bsplit(W[k * 128 + n], Bh[i], Bl[i]);
}
// GAT W0 [8][128][16] -> B[n][k], n = h*16+f
__global__ void k_packW0split(const float* __restrict__ W0) {
    int i = blockIdx.x * blockDim.x + threadIdx.x;
    if (i >= 128 * 128) return;
    int n = i >> 7, k = i & 127;
    int h = n >> 4, f = n & 15;
    bsplit(W0[h * (Dd * 16) + k * 16 + f], g_B0h[i], g_B0l[i]);
}
// W1 [8][128][128] -> Bt[n][k] (k = h*128 + kk), split bf16 hi/lo
__global__ void k_packW1(const float* __restrict__ W1) {
    int i = blockIdx.x * blockDim.x + threadIdx.x;
    if (i >= 128 * 1024) return;
    int n = i >> 10, k = i & 1023;
    int h = k >> 7, kk = k & 127;
    bsplit(W1[h * (Dd * Dd) + kk * Dd + n], g_Bth[i], g_Btl[i]);
}
__global__ void k_uv1(const float* __restrict__ W1,
                      const float* __restrict__ a_s, const float* __restrict__ a_d) {
    int i = blockIdx.x * blockDim.x + threadIdx.x;
    if (i >= Hh * Dd) return;
    int h = i >> 7, k = i & 127;
    const float* w = &W1[h * Dd * Dd + k * Dd];
    float su = 0.f, sv = 0.f;
    #pragma unroll 8
    for (int f = 0; f < Dd; f++) {
        float v = __ldg(&w[f]);
        su = fmaf(v, __ldg(&a_s[h * Dd + f]), su);
        sv = fmaf(v, __ldg(&a_d[h * Dd + f]), sv);
    }
    g_u1[i] = su; g_v1[i] = sv;
}

// ---------------- es / ed ----------------
__global__ void k_esed0(const float* __restrict__ a_s, const float* __restrict__ a_d) {
    int i = blockIdx.x * blockDim.x + threadIdx.x;
    if (i >= Nn * Hh) return;
    int n = i >> 3, h = i & 7;
    const float* w = &g_Wh0[n * Dd + h * 16];
    float s = 0.f, d = 0.f;
    #pragma unroll
    for (int f = 0; f < 16; f++) {
        float v = w[f];
        s = fmaf(v, __ldg(&a_s[h * 16 + f]), s);
        d = fmaf(v, __ldg(&a_d[h * 16 + f]), d);
    }
    g_es[i] = s; g_ed[i] = d;
}
__global__ void k_esed1() {
    int i = blockIdx.x * blockDim.x + threadIdx.x;
    if (i >= Nn * Hh) return;
    int n = i >> 3, h = i & 7;
    const float* x = &g_x1[n * Dd];
    const float* u = &g_u1[h * Dd];
    const float* v = &g_v1[h * Dd];
    float s = 0.f, d = 0.f;
    #pragma unroll 8
    for (int k = 0; k < Dd; k++) {
        float xv = x[k];
        s = fmaf(xv, u[k], s);
        d = fmaf(xv, v[k], d);
    }
    g_es[i] = s; g_ed[i] = d;
}

// ---------------- attention softmax: warp per dst row ----------------
__global__ void k_att() {
    int wid  = (blockIdx.x * blockDim.x + threadIdx.x) >> 5;
    int lane = threadIdx.x & 31;
    if (wid >= Nn) return;
    int p0 = g_rowptr[wid], p1 = g_rowptr[wid + 1];
    int deg = p1 - p0;
    if (deg == 0) return;
    int h = lane & 7;
    float edv = g_ed[wid * 8 + h];
    int tot = deg * 8;
    float m = -1e30f;
    for (int i = lane; i < tot; i += 32) {
        int e = i >> 3;
        float x = g_es[g_ssrc[p0 + e] * 8 + h] + edv;
        x = x > 0.f ? x : 0.2f * x;
        g_att[(p0 + e) * 8 + h] = x;
        m = fmaxf(m, x);
    }
    m = fmaxf(m, __shfl_xor_sync(0xffffffffu, m, 8));
    m = fmaxf(m, __shfl_xor_sync(0xffffffffu, m, 16));
    float s = 0.f;
    for (int i = lane; i < tot; i += 32) {
        int e = i >> 3;
        s += __expf(g_att[(p0 + e) * 8 + h] - m);
    }
    s += __shfl_xor_sync(0xffffffffu, s, 8);
    s += __shfl_xor_sync(0xffffffffu, s, 16);
    float inv = 1.f / fmaxf(s, 1e-16f);
    for (int i = lane; i < tot; i += 32) {
        int e = i >> 3;
        g_att[(p0 + e) * 8 + h] = __expf(g_att[(p0 + e) * 8 + h] - m) * inv;
    }
}

// ---------------- aggregations (block per dst row, no atomics) ----------------
__global__ void k_agg_gat0() {
    int r = blockIdx.x, t = threadIdx.x;
    int p0 = g_rowptr[r], p1 = g_rowptr[r + 1];
    int h = t >> 4;
    float acc = 0.f;
    #pragma unroll 4
    for (int p = p0; p < p1; p++)
        acc = fmaf(g_att[p * 8 + h], g_Wh0[g_ssrc[p] * Dd + t], acc);
    g_x1[r * Dd + t] = acc > 0.f ? acc : expm1f(acc);
}
__global__ void k_agg_gat1() {
    int r = blockIdx.x, t = threadIdx.x;
    int p0 = g_rowptr[r], p1 = g_rowptr[r + 1];
    float acc[8] = {0.f, 0.f, 0.f, 0.f, 0.f, 0.f, 0.f, 0.f};
    for (int p = p0; p < p1; p++) {
        float v = g_x1[g_ssrc[p] * Dd + t];
        float4 a0 = *(const float4*)&g_att[p * 8];
        float4 a1 = *(const float4*)&g_att[p * 8 + 4];
        acc[0] = fmaf(a0.x, v, acc[0]); acc[1] = fmaf(a0.y, v, acc[1]);
        acc[2] = fmaf(a0.z, v, acc[2]); acc[3] = fmaf(a0.w, v, acc[3]);
        acc[4] = fmaf(a1.x, v, acc[4]); acc[5] = fmaf(a1.y, v, acc[5]);
        acc[6] = fmaf(a1.z, v, acc[6]); acc[7] = fmaf(a1.w, v, acc[7]);
    }
    int base = r * 1024 + t;
    #pragma unroll
    for (int h = 0; h < 8; h++)
        bsplit(acc[h], g_yh[base + h * Dd], g_yl[base + h * Dd]);
}
// wsplit != 0: also emit split-bf16 copy of output (for next GEMM's A operand)
__global__ void k_agg_gcn(const float* __restrict__ hsrc, float* __restrict__ out,
                          __nv_bfloat16* __restrict__ oh, __nv_bfloat16* __restrict__ ol,
                          int wsplit) {
    __shared__ float red[128];
    int r = blockIdx.x, t = threadIdx.x;
    int p0 = g_rowptr[r], p1 = g_rowptr[r + 1];
    float ds = 0.f;
    for (int p = p0 + t; p < p1; p += 128) ds += g_sw[p];
    red[t] = ds;
    __syncthreads();
    for (int d = 64; d > 0; d >>= 1) {
        if (t < d) red[t] += red[t + d];
        __syncthreads();
    }
    float inv = 1.f / fmaxf(red[0], 1e-16f);
    float acc = 0.f;
    #pragma unroll 4
    for (int p = p0; p < p1; p++)
        acc = fmaf(g_sw[p] * inv, hsrc[g_ssrc[p] * Dd + t], acc);
    float v = fmaxf(acc, 0.f);
    if (wsplit) bsplit(v, oh[r * Dd + t], ol[r * Dd + t]);
    else        out[r * Dd + t] = v;
}

// ---------------- mma.sync split-bf16 GEMM: C[M,128] = alpha * A @ B^T ----------------
// A = (Ah|Al)[M,Kel] bf16 K-major; B = (Bh|Bl)[128,Kel] bf16 K-major.
// 3 passes: hi*hi + hi*lo + lo*hi. fp32 accumulate.
// 128x128 block tile, 8 warps 2(m)x4(n), warp tile 64x32 (4x4 m16n8k16).
// K chunks of 64, cp.async double-buffered; SMEM pitch 144B.
#define TCH 64
#define PITCHB 144
#define TILE_BYTES (128 * PITCHB)        // 18432
#define BUF_BYTES (4 * TILE_BYTES)

extern "C" __global__ __launch_bounds__(256, 1) void gemm_tc(
    const __nv_bfloat16* __restrict__ Ah, const __nv_bfloat16* __restrict__ Al,
    const __nv_bfloat16* __restrict__ Bh, const __nv_bfloat16* __restrict__ Bl,
    float* __restrict__ C, float alpha, int M, int Kel)
{
    extern __shared__ char smem[];
    const unsigned sbase = s2u(smem);
    const int tid  = threadIdx.x;
    const int wid  = tid >> 5;
    const int lane = tid & 31;
    const int row0 = blockIdx.x * 128;
    const int mw = wid & 1, nw = wid >> 1;
    const int m0 = mw * 64, n0 = nw * 32;
    const int NCH = Kel >> 6;

    const __nv_bfloat16* srcs[4] = { Ah, Al, Bh, Bl };

    auto load_chunk = [&](int c, int buf) {
        unsigned bb = sbase + buf * BUF_BYTES;
        #pragma unroll
        for (int i = 0; i < 16; i++) {
            int o   = tid + 256 * i;
            int tl  = o >> 10;
            int r   = (o & 1023) >> 3;
            int seg = o & 7;
            unsigned dst = bb + tl * TILE_BYTES + r * PITCHB + seg * 16;
            size_t goff = (size_t)c * TCH + seg * 8;
            const __nv_bfloat16* s;
            int ok = 16;
            if (tl < 2) {
                int gr = row0 + r;
                s = srcs[tl] + (size_t)gr * Kel + goff;
                if (gr >= M) ok = 0;
            } else {
                s = srcs[tl] + (size_t)r * Kel + goff;
            }
            cpa16(dst, s, ok);
        }
        cpa_commit();
    };

    float acc[4][4][4] = {};

    load_chunk(0, 0);

    for (int c = 0; c < NCH; c++) {
        int buf = c & 1;
        if (c + 1 < NCH) { load_chunk(c + 1, buf ^ 1); cpa_wait<1>(); }
        else             { cpa_wait<0>(); }
        __syncthreads();

        unsigned bb  = sbase + buf * BUF_BYTES;
        unsigned uAh = bb;
        unsigned uAl = bb + TILE_BYTES;
        unsigned uBh = bb + 2 * TILE_BYTES;
        unsigned uBl = bb + 3 * TILE_BYTES;

        int l15 = lane & 15;
        #pragma unroll
        for (int ks = 0; ks < 4; ks++) {
            unsigned ah[4][4], al[4][4], bh[4][2], bl[4][2];
            unsigned aoff = (unsigned)(m0 + l15) * PITCHB + ks * 32 + (lane >> 4) * 16;
            #pragma unroll
            for (int i = 0; i < 4; i++) {
                ldmx4(ah[i], uAh + aoff + i * 16 * PITCHB);
                ldmx4(al[i], uAl + aoff + i * 16 * PITCHB);
            }
            unsigned boff = (unsigned)(n0 + (l15 & 7)) * PITCHB + ks * 32 + (l15 >> 3) * 16;
            #pragma unroll
            for (int j = 0; j < 4; j++) {
                ldmx2(bh[j], uBh + boff + j * 8 * PITCHB);
                ldmx2(bl[j], uBl + boff + j * 8 * PITCHB);
            }
            #pragma unroll
            for (int i = 0; i < 4; i++)
                #pragma unroll
                for (int j = 0; j < 4; j++) {
                    mma16816(acc[i][j], ah[i], bh[j]);
                    mma16816(acc[i][j], ah[i], bl[j]);
                    mma16816(acc[i][j], al[i], bh[j]);
                }
        }
        __syncthreads();
    }

    int rb = row0 + m0 + (lane >> 2);
    int cb = n0 + (lane & 3) * 2;
    #pragma unroll
    for (int i = 0; i < 4; i++) {
        #pragma unroll
        for (int j = 0; j < 4; j++) {
            int r1 = rb + i * 16, c1 = cb + j * 8;
            if (r1 < M)
                *(float2*)&C[(size_t)r1 * 128 + c1] =
                    make_float2(acc[i][j][0] * alpha, acc[i][j][1] * alpha);
            int r2 = r1 + 8;
            if (r2 < M)
                *(float2*)&C[(size_t)r2 * 128 + c1] =
                    make_float2(acc[i][j][2] * alpha, acc[i][j][3] * alpha);
        }
    }
}

// ---------------- final elementwise max ----------------
__global__ void k_final(float* __restrict__ out) {
    int i = blockIdx.x * blockDim.x + threadIdx.x;
    if (i < Nn * Dd) out[i] = fmaxf(out[i], g_x2b[i]);
}

// ---------------- launch ----------------
extern "C" void kernel_launch(void* const* d_in, const int* in_sizes, int n_in,
                              void* d_out, int out_size) {
    const float* x   = (const float*)d_in[0];
    const int*   ei  = (const int*)d_in[1];
    const float* ew  = (const float*)d_in[2];
    const float* W0  = (const float*)d_in[3];
    const float* a0s = (const float*)d_in[4];
    const float* a0d = (const float*)d_in[5];
    const float* W1  = (const float*)d_in[6];
    const float* a1s = (const float*)d_in[7];
    const float* a1d = (const float*)d_in[8];
    const float* gW0 = (const float*)d_in[9];
    const float* gW1 = (const float*)d_in[10];
    float* out = (float*)d_out;

    float *pWh0, *pHg, *pX2b;
    __nv_bfloat16 *pYh, *pYl, *pXh, *pXl, *pX2h, *pX2l;
    __nv_bfloat16 *pBth, *pBtl, *pB0h, *pB0l, *pBg0h, *pBg0l, *pBg1h, *pBg1l;
    cudaGetSymbolAddress((void**)&pWh0,  g_Wh0);
    cudaGetSymbolAddress((void**)&pHg,   g_hg);
    cudaGetSymbolAddress((void**)&pX2b,  g_x2b);
    cudaGetSymbolAddress((void**)&pYh,   g_yh);
    cudaGetSymbolAddress((void**)&pYl,   g_yl);
    cudaGetSymbolAddress((void**)&pXh,   g_xh);
    cudaGetSymbolAddress((void**)&pXl,   g_xl);
    cudaGetSymbolAddress((void**)&pX2h,  g_x2h);
    cudaGetSymbolAddress((void**)&pX2l,  g_x2l);
    cudaGetSymbolAddress((void**)&pBth,  g_Bth);
    cudaGetSymbolAddress((void**)&pBtl,  g_Btl);
    cudaGetSymbolAddress((void**)&pB0h,  g_B0h);
    cudaGetSymbolAddress((void**)&pB0l,  g_B0l);
    cudaGetSymbolAddress((void**)&pBg0h, g_Bg0h);
    cudaGetSymbolAddress((void**)&pBg0l, g_Bg0l);
    cudaGetSymbolAddress((void**)&pBg1h, g_Bg1h);
    cudaGetSymbolAddress((void**)&pBg1l, g_Bg1l);

    const int gA = (Nn + 127) / 128;
    const int SMEM_TC = 2 * BUF_BYTES;   // 147456 bytes
    cudaFuncSetAttribute(gemm_tc, cudaFuncAttributeMaxDynamicSharedMemorySize, SMEM_TC);

    // edge-index normalization + CSR build
    k_detect <<<1, 32>>>(ei);
    k_convert<<<(2 * Ee + 255) / 256, 256>>>(ei);
    k_zero   <<<(Nn + 255) / 256, 256>>>();
    k_count  <<<(Ee + 255) / 256, 256>>>();
    k_scan   <<<1, 1024>>>();
    k_scatter<<<(Ee + 255) / 256, 256>>>(ew);

    // input split + weight packs
    k_splitx    <<<(Nn * Dd + 255) / 256, 256>>>(x);
    k_packW0split<<<(128 * 128 + 255) / 256, 256>>>(W0);
    k_packWsplit<<<(128 * 128 + 255) / 256, 256>>>(gW0, pBg0h, pBg0l);
    k_packWsplit<<<(128 * 128 + 255) / 256, 256>>>(gW1, pBg1h, pBg1l);
    k_packW1    <<<(128 * 1024 + 255) / 256, 256>>>(W1);

    // GAT layer 0
    gemm_tc  <<<gA, 256, SMEM_TC>>>(pXh, pXl, pB0h, pB0l, pWh0, 1.f, Nn, 128);
    k_esed0  <<<(Nn * Hh + 255) / 256, 256>>>(a0s, a0d);
    k_att    <<<(Nn + 7) / 8, 256>>>();
    k_agg_gat0<<<Nn, 128>>>();

    // GCN layer 0
    gemm_tc  <<<gA, 256, SMEM_TC>>>(pXh, pXl, pBg0h, pBg0l, pHg, 1.f, Nn, 128);
    k_agg_gcn<<<Nn, 128>>>(pHg, (float*)0, pX2h, pX2l, 1);

    // GAT layer 1: aggregate (split-bf16) then one tensor-core GEMM
    k_uv1    <<<4, 256>>>(W1, a1s, a1d);
    k_esed1  <<<(Nn * Hh + 255) / 256, 256>>>();
    k_att    <<<(Nn + 7) / 8, 256>>>();
    k_agg_gat1<<<Nn, 128>>>();
    gemm_tc  <<<gA, 256, SMEM_TC>>>(pYh, pYl, pBth, pBtl, out, 0.125f, Nn, 1024);

    // GCN layer 1
    gemm_tc  <<<gA, 256, SMEM_TC>>>(pX2h, pX2l, pBg1h, pBg1l, pHg, 1.f, Nn, 128);
    k_agg_gcn<<<Nn, 128>>>(pHg, pX2b, (__nv_bfloat16*)0, (__nv_bfloat16*)0, 0);

    // final: max(gat, gcn)
    k_final  <<<(Nn * Dd + 255) / 256, 256>>>(out);
}

// round 15
// speedup vs baseline: 1.6212x; 1.2461x over previous
#include <cuda_runtime.h>
#include <cuda_bf16.h>
#include <math.h>

#define Nn 50000
#define Ee 800000
#define Hh 8
#define Dd 128

// ---------------- scratch (static device globals; no runtime alloc) ----------------
__device__ int   g_is64;
__device__ int   g_eidx[2 * Ee];
__device__ int   g_rowcnt[Nn];
__device__ int   g_cursor[Nn];
__device__ int   g_rowptr[Nn + 1];
__device__ int   g_bsum[64];
__device__ int   g_boff[64];
__device__ int   g_ssrc[Ee];
__device__ float g_sw[Ee];
__device__ float g_Wh0[Nn * Dd];
__device__ float g_es[Nn * Hh];
__device__ float g_ed[Nn * Hh];
__device__ float g_att[Ee * Hh];
__device__ float g_x1[Nn * Dd];                 // GAT layer-0 output (post-ELU)
__device__ __nv_bfloat16 g_xh[Nn * Dd];         // split input x (hi/lo)
__device__ __nv_bfloat16 g_xl[Nn * Dd];
__device__ __nv_bfloat16 g_x2h[Nn * Dd];        // split GCN layer-1 output
__device__ __nv_bfloat16 g_x2l[Nn * Dd];
__device__ __nv_bfloat16 g_yh[Nn * 1024];       // split aggregated x1 (per head)
__device__ __nv_bfloat16 g_yl[Nn * 1024];
__device__ __nv_bfloat16 g_Bth[128 * 1024];     // W1 packed [n][k]
__device__ __nv_bfloat16 g_Btl[128 * 1024];
__device__ __nv_bfloat16 g_B0h[128 * 128];      // W0 packed [n][k]
__device__ __nv_bfloat16 g_B0l[128 * 128];
__device__ __nv_bfloat16 g_Bg0h[128 * 128];     // gcn_W0 packed [n][k]
__device__ __nv_bfloat16 g_Bg0l[128 * 128];
__device__ __nv_bfloat16 g_Bg1h[128 * 128];     // gcn_W1 packed [n][k]
__device__ __nv_bfloat16 g_Bg1l[128 * 128];
__device__ float g_hg[Nn * Dd];
__device__ float g_x2b[Nn * Dd];
__device__ float g_u1[Hh * Dd];
__device__ float g_v1[Hh * Dd];

// ---------------- base-target PTX helpers (sm_80+ features only) ----------------
__device__ __forceinline__ unsigned s2u(const void* p) {
    unsigned a;
    asm("{ .reg .u64 t; cvta.to.shared.u64 t, %1; cvt.u32.u64 %0, t; }" : "=r"(a) : "l"(p));
    return a;
}
__device__ __forceinline__ void cpa16(unsigned dst, const void* src, int szsrc) {
    asm volatile("cp.async.cg.shared.global [%0], [%1], 16, %2;"
                 :: "r"(dst), "l"(src), "r"(szsrc) : "memory");
}
__device__ __forceinline__ void cpa_commit() {
    asm volatile("cp.async.commit_group;" ::: "memory");
}
template <int N>
__device__ __forceinline__ void cpa_wait() {
    asm volatile("cp.async.wait_group %0;" :: "n"(N) : "memory");
}
__device__ __forceinline__ void ldmx4(unsigned* r, unsigned addr) {
    asm volatile("ldmatrix.sync.aligned.m8n8.x4.shared.b16 {%0,%1,%2,%3}, [%4];"
                 : "=r"(r[0]), "=r"(r[1]), "=r"(r[2]), "=r"(r[3]) : "r"(addr));
}
__device__ __forceinline__ void ldmx2(unsigned* r, unsigned addr) {
    asm volatile("ldmatrix.sync.aligned.m8n8.x2.shared.b16 {%0,%1}, [%2];"
                 : "=r"(r[0]), "=r"(r[1]) : "r"(addr));
}
__device__ __forceinline__ void mma16816(float* c, const unsigned* a, const unsigned* b) {
    asm volatile(
        "mma.sync.aligned.m16n8k16.row.col.f32.bf16.bf16.f32 "
        "{%0,%1,%2,%3}, {%4,%5,%6,%7}, {%8,%9}, {%0,%1,%2,%3};"
        : "+f"(c[0]), "+f"(c[1]), "+f"(c[2]), "+f"(c[3])
        : "r"(a[0]), "r"(a[1]), "r"(a[2]), "r"(a[3]), "r"(b[0]), "r"(b[1]));
}
__device__ __forceinline__ void bsplit(float v, __nv_bfloat16& hi, __nv_bfloat16& lo) {
    hi = __float2bfloat16(v);
    lo = __float2bfloat16(v - __bfloat162float(hi));
}

// ---------------- edge-index dtype detection ----------------
__global__ void k_detect(const int* __restrict__ ei32) {
    if (threadIdx.x == 0 && blockIdx.x == 0) {
        int is64 = 1;
        for (int i = 0; i < 256; i++)
            if (ei32[2 * i + 1] != 0) { is64 = 0; break; }
        g_is64 = is64;
    }
}

// ---------------- CSR build ----------------
__global__ void k_zero() {
    int i = blockIdx.x * blockDim.x + threadIdx.x;
    if (i < Nn) { g_rowcnt[i] = 0; g_cursor[i] = 0; }
}
// fused convert + degree count (rowcnt must be zeroed first)
__global__ void k_convcnt(const int* __restrict__ ei32) {
    int i = blockIdx.x * blockDim.x + threadIdx.x;
    if (i >= Ee) return;
    int s = g_is64 ? ei32[2 * i] : ei32[i];
    int d = g_is64 ? ei32[2 * (Ee + i)] : ei32[Ee + i];
    g_eidx[i] = s;
    g_eidx[Ee + i] = d;
    atomicAdd(&g_rowcnt[d], 1);
}
// 3-phase parallel scan over rowcnt -> rowptr
__global__ void k_scan1() {                  // grid 49, block 1024: per-block inclusive scan
    __shared__ int tmp[1024];
    int b = blockIdx.x, t = threadIdx.x;
    int i = b * 1024 + t;
    tmp[t] = (i < Nn) ? g_rowcnt[i] : 0;
    __syncthreads();
    for (int d = 1; d < 1024; d <<= 1) {
        int add = (t >= d) ? tmp[t - d] : 0;
        __syncthreads();
        tmp[t] += add;
        __syncthreads();
    }
    if (i < Nn) g_rowptr[i + 1] = tmp[t];
    if (t == 1023) g_bsum[b] = tmp[1023];
}
__global__ void k_scan2() {                  // 1 block, 64 threads: scan block sums
    __shared__ int tmp[64];
    int t = threadIdx.x;
    const int nb = (Nn + 1023) / 1024;
    tmp[t] = (t < nb) ? g_bsum[t] : 0;
    __syncthreads();
    for (int d = 1; d < 64; d <<= 1) {
        int add = (t >= d) ? tmp[t - d] : 0;
        __syncthreads();
        tmp[t] += add;
        __syncthreads();
    }
    g_boff[t] = (t == 0) ? 0 : tmp[t - 1];
}
__global__ void k_scan3() {                  // add block offsets
    int b = blockIdx.x, t = threadIdx.x;
    int i = b * 1024 + t;
    if (i < Nn) g_rowptr[i + 1] += g_boff[b];
    if (b == 0 && t == 0) g_rowptr[0] = 0;
}
__global__ void k_scatter(const float* __restrict__ w) {
    int i = blockIdx.x * blockDim.x + threadIdx.x;
    if (i >= Ee) return;
    int s = g_eidx[i];
    int d = g_eidx[Ee + i];
    int p = g_rowptr[d] + atomicAdd(&g_cursor[d], 1);
    g_ssrc[p] = s;
    g_sw[p]   = w[i];
}
// normalize edge weights in place by in-degree weight sum (used by both GCN layers)
__global__ void k_normw() {
    __shared__ float red[128];
    int r = blockIdx.x, t = threadIdx.x;
    int p0 = g_rowptr[r], p1 = g_rowptr[r + 1];
    float ds = 0.f;
    for (int p = p0 + t; p < p1; p += 128) ds += g_sw[p];
    red[t] = ds;
    __syncthreads();
    for (int d = 64; d > 0; d >>= 1) {
        if (t < d) red[t] += red[t + d];
        __syncthreads();
    }
    float inv = 1.f / fmaxf(red[0], 1e-16f);
    for (int p = p0 + t; p < p1; p += 128) g_sw[p] *= inv;
}

// ---------------- input split + weight packs ----------------
__global__ void k_splitx(const float* __restrict__ x) {
    int i = blockIdx.x * blockDim.x + threadIdx.x;
    if (i >= Nn * Dd) return;
    bsplit(x[i], g_xh[i], g_xl[i]);
}
__global__ void k_packWsplit(const float* __restrict__ W,
                             __nv_bfloat16* __restrict__ Bh, __nv_bfloat16* __restrict__ Bl) {
    int i = blockIdx.x * blockDim.x + threadIdx.x;
    if (i >= 128 * 128) return;
    int n = i >> 7, k = i & 127;
    bsplit(W[k * 128 + n], Bh[i], Bl[i]);
}
__global__ void k_packW0split(const float* __restrict__ W0) {
    int i = blockIdx.x * blockDim.x + threadIdx.x;
    if (i >= 128 * 128) return;
    int n = i >> 7, k = i & 127;
    int h = n >> 4, f = n & 15;
    bsplit(W0[h * (Dd * 16) + k * 16 + f], g_B0h[i], g_B0l[i]);
}
__global__ void k_packW1(const float* __restrict__ W1) {
    int i = blockIdx.x * blockDim.x + threadIdx.x;
    if (i >= 128 * 1024) return;
    int n = i >> 10, k = i & 1023;
    int h = k >> 7, kk = k & 127;
    bsplit(W1[h * (Dd * Dd) + kk * Dd + n], g_Bth[i], g_Btl[i]);
}
__global__ void k_uv1(const float* __restrict__ W1,
                      const float* __restrict__ a_s, const float* __restrict__ a_d) {
    int i = blockIdx.x * blockDim.x + threadIdx.x;
    if (i >= Hh * Dd) return;
    int h = i >> 7, k = i & 127;
    const float* w = &W1[h * Dd * Dd + k * Dd];
    float su = 0.f, sv = 0.f;
    #pragma unroll 8
    for (int f = 0; f < Dd; f++) {
        float v = __ldg(&w[f]);
        su = fmaf(v, __ldg(&a_s[h * Dd + f]), su);
        sv = fmaf(v, __ldg(&a_d[h * Dd + f]), sv);
    }
    g_u1[i] = su; g_v1[i] = sv;
}

// ---------------- es / ed ----------------
__global__ void k_esed0(const float* __restrict__ a_s, const float* __restrict__ a_d) {
    int i = blockIdx.x * blockDim.x + threadIdx.x;
    if (i >= Nn * Hh) return;
    int n = i >> 3, h = i & 7;
    const float* w = &g_Wh0[n * Dd + h * 16];
    float s = 0.f, d = 0.f;
    #pragma unroll
    for (int f = 0; f < 16; f++) {
        float v = w[f];
        s = fmaf(v, __ldg(&a_s[h * 16 + f]), s);
        d = fmaf(v, __ldg(&a_d[h * 16 + f]), d);
    }
    g_es[i] = s; g_ed[i] = d;
}
// warp per node: x1 row read once for all 8 heads; u1/v1 cached in SMEM
__global__ __launch_bounds__(512) void k_esed1() {
    __shared__ float su[1024], sv[1024];
    int t = threadIdx.x;
    for (int i = t; i < 1024; i += 512) { su[i] = g_u1[i]; sv[i] = g_v1[i]; }
    __syncthreads();
    int w = blockIdx.x * 16 + (t >> 5);
    if (w >= Nn) return;
    int lane = t & 31;
    float4 xv = *(const float4*)&g_x1[w * Dd + lane * 4];
    #pragma unroll
    for (int h = 0; h < 8; h++) {
        const float* u = &su[h * 128 + lane * 4];
        const float* v = &sv[h * 128 + lane * 4];
        float s = xv.x * u[0] + xv.y * u[1] + xv.z * u[2] + xv.w * u[3];
        float d = xv.x * v[0] + xv.y * v[1] + xv.z * v[2] + xv.w * v[3];
        #pragma unroll
        for (int o = 16; o; o >>= 1) {
            s += __shfl_xor_sync(0xffffffffu, s, o);
            d += __shfl_xor_sync(0xffffffffu, d, o);
        }
        if (lane == 0) { g_es[w * 8 + h] = s; g_ed[w * 8 + h] = d; }
    }
}

// ---------------- attention softmax: warp per dst row ----------------
__global__ void k_att() {
    int wid  = (blockIdx.x * blockDim.x + threadIdx.x) >> 5;
    int lane = threadIdx.x & 31;
    if (wid >= Nn) return;
    int p0 = g_rowptr[wid], p1 = g_rowptr[wid + 1];
    int deg = p1 - p0;
    if (deg == 0) return;
    int h = lane & 7;
    float edv = g_ed[wid * 8 + h];
    int tot = deg * 8;
    float m = -1e30f;
    for (int i = lane; i < tot; i += 32) {
        int e = i >> 3;
        float x = g_es[g_ssrc[p0 + e] * 8 + h] + edv;
        x = x > 0.f ? x : 0.2f * x;
        g_att[(p0 + e) * 8 + h] = x;
        m = fmaxf(m, x);
    }
    m = fmaxf(m, __shfl_xor_sync(0xffffffffu, m, 8));
    m = fmaxf(m, __shfl_xor_sync(0xffffffffu, m, 16));
    float s = 0.f;
    for (int i = lane; i < tot; i += 32) {
        int e = i >> 3;
        s += __expf(g_att[(p0 + e) * 8 + h] - m);
    }
    s += __shfl_xor_sync(0xffffffffu, s, 8);
    s += __shfl_xor_sync(0xffffffffu, s, 16);
    float inv = 1.f / fmaxf(s, 1e-16f);
    for (int i = lane; i < tot; i += 32) {
        int e = i >> 3;
        g_att[(p0 + e) * 8 + h] = __expf(g_att[(p0 + e) * 8 + h] - m) * inv;
    }
}

// ---------------- aggregations (block per dst row, no atomics) ----------------
__global__ void k_agg_gat0() {
    int r = blockIdx.x, t = threadIdx.x;
    int p0 = g_rowptr[r], p1 = g_rowptr[r + 1];
    int h = t >> 4;
    float acc = 0.f;
    #pragma unroll 4
    for (int p = p0; p < p1; p++)
        acc = fmaf(g_att[p * 8 + h], g_Wh0[g_ssrc[p] * Dd + t], acc);
    g_x1[r * Dd + t] = acc > 0.f ? acc : expm1f(acc);
}
__global__ void k_agg_gat1() {
    int r = blockIdx.x, t = threadIdx.x;
    int p0 = g_rowptr[r], p1 = g_rowptr[r + 1];
    float acc[8] = {0.f, 0.f, 0.f, 0.f, 0.f, 0.f, 0.f, 0.f};
    for (int p = p0; p < p1; p++) {
        float v = g_x1[g_ssrc[p] * Dd + t];
        float4 a0 = *(const float4*)&g_att[p * 8];
        float4 a1 = *(const float4*)&g_att[p * 8 + 4];
        acc[0] = fmaf(a0.x, v, acc[0]); acc[1] = fmaf(a0.y, v, acc[1]);
        acc[2] = fmaf(a0.z, v, acc[2]); acc[3] = fmaf(a0.w, v, acc[3]);
        acc[4] = fmaf(a1.x, v, acc[4]); acc[5] = fmaf(a1.y, v, acc[5]);
        acc[6] = fmaf(a1.z, v, acc[6]); acc[7] = fmaf(a1.w, v, acc[7]);
    }
    int base = r * 1024 + t;
    #pragma unroll
    for (int h = 0; h < 8; h++)
        bsplit(acc[h], g_yh[base + h * Dd], g_yl[base + h * Dd]);
}
// weights pre-normalized by k_normw; pure weighted gather + ReLU
__global__ void k_agg_gcn(const float* __restrict__ hsrc, float* __restrict__ out,
                          __nv_bfloat16* __restrict__ oh, __nv_bfloat16* __restrict__ ol,
                          int wsplit) {
    int r = blockIdx.x, t = threadIdx.x;
    int p0 = g_rowptr[r], p1 = g_rowptr[r + 1];
    float acc = 0.f;
    #pragma unroll 4
    for (int p = p0; p < p1; p++)
        acc = fmaf(g_sw[p], hsrc[g_ssrc[p] * Dd + t], acc);
    float v = fmaxf(acc, 0.f);
    if (wsplit) bsplit(v, oh[r * Dd + t], ol[r * Dd + t]);
    else        out[r * Dd + t] = v;
}

// ---------------- mma.sync split-bf16 GEMM: C[M,128] = alpha * A @ B^T ----------------
// Optional Cmax: C = max(alpha*A@B^T, Cmax) elementwise (fuses the final branch-max).
#define TCH 64
#define PITCHB 144
#define TILE_BYTES (128 * PITCHB)        // 18432
#define BUF_BYTES (4 * TILE_BYTES)

extern "C" __global__ __launch_bounds__(256, 1) void gemm_tc(
    const __nv_bfloat16* __restrict__ Ah, const __nv_bfloat16* __restrict__ Al,
    const __nv_bfloat16* __restrict__ Bh, const __nv_bfloat16* __restrict__ Bl,
    float* __restrict__ C, const float* __restrict__ Cmax, float alpha, int M, int Kel)
{
    extern __shared__ char smem[];
    const unsigned sbase = s2u(smem);
    const int tid  = threadIdx.x;
    const int wid  = tid >> 5;
    const int lane = tid & 31;
    const int row0 = blockIdx.x * 128;
    const int mw = wid & 1, nw = wid >> 1;
    const int m0 = mw * 64, n0 = nw * 32;
    const int NCH = Kel >> 6;

    const __nv_bfloat16* srcs[4] = { Ah, Al, Bh, Bl };

    auto load_chunk = [&](int c, int buf) {
        unsigned bb = sbase + buf * BUF_BYTES;
        #pragma unroll
        for (int i = 0; i < 16; i++) {
            int o   = tid + 256 * i;
            int tl  = o >> 10;
            int r   = (o & 1023) >> 3;
            int seg = o & 7;
            unsigned dst = bb + tl * TILE_BYTES + r * PITCHB + seg * 16;
            size_t goff = (size_t)c * TCH + seg * 8;
            const __nv_bfloat16* s;
            int ok = 16;
            if (tl < 2) {
                int gr = row0 + r;
                s = srcs[tl] + (size_t)gr * Kel + goff;
                if (gr >= M) ok = 0;
            } else {
                s = srcs[tl] + (size_t)r * Kel + goff;
            }
            cpa16(dst, s, ok);
        }
        cpa_commit();
    };

    float acc[4][4][4] = {};

    load_chunk(0, 0);

    for (int c = 0; c < NCH; c++) {
        int buf = c & 1;
        if (c + 1 < NCH) { load_chunk(c + 1, buf ^ 1); cpa_wait<1>(); }
        else             { cpa_wait<0>(); }
        __syncthreads();

        unsigned bb  = sbase + buf * BUF_BYTES;
        unsigned uAh = bb;
        unsigned uAl = bb + TILE_BYTES;
        unsigned uBh = bb + 2 * TILE_BYTES;
        unsigned uBl = bb + 3 * TILE_BYTES;

        int l15 = lane & 15;
        #pragma unroll
        for (int ks = 0; ks < 4; ks++) {
            unsigned ah[4][4], al[4][4], bh[4][2], bl[4][2];
            unsigned aoff = (unsigned)(m0 + l15) * PITCHB + ks * 32 + (lane >> 4) * 16;
            #pragma unroll
            for (int i = 0; i < 4; i++) {
                ldmx4(ah[i], uAh + aoff + i * 16 * PITCHB);
                ldmx4(al[i], uAl + aoff + i * 16 * PITCHB);
            }
            unsigned boff = (unsigned)(n0 + (l15 & 7)) * PITCHB + ks * 32 + (l15 >> 3) * 16;
            #pragma unroll
            for (int j = 0; j < 4; j++) {
                ldmx2(bh[j], uBh + boff + j * 8 * PITCHB);
                ldmx2(bl[j], uBl + boff + j * 8 * PITCHB);
            }
            #pragma unroll
            for (int i = 0; i < 4; i++)
                #pragma unroll
                for (int j = 0; j < 4; j++) {
                    mma16816(acc[i][j], ah[i], bh[j]);
                    mma16816(acc[i][j], ah[i], bl[j]);
                    mma16816(acc[i][j], al[i], bh[j]);
                }
        }
        __syncthreads();
    }

    int rb = row0 + m0 + (lane >> 2);
    int cb = n0 + (lane & 3) * 2;
    #pragma unroll
    for (int i = 0; i < 4; i++) {
        #pragma unroll
        for (int j = 0; j < 4; j++) {
            int r1 = rb + i * 16, c1 = cb + j * 8;
            if (r1 < M) {
                float2 v = make_float2(acc[i][j][0] * alpha, acc[i][j][1] * alpha);
                if (Cmax) {
                    float2 m2 = *(const float2*)&Cmax[(size_t)r1 * 128 + c1];
                    v.x = fmaxf(v.x, m2.x); v.y = fmaxf(v.y, m2.y);
                }
                *(float2*)&C[(size_t)r1 * 128 + c1] = v;
            }
            int r2 = r1 + 8;
            if (r2 < M) {
                float2 v = make_float2(acc[i][j][2] * alpha, acc[i][j][3] * alpha);
                if (Cmax) {
                    float2 m2 = *(const float2*)&Cmax[(size_t)r2 * 128 + c1];
                    v.x = fmaxf(v.x, m2.x); v.y = fmaxf(v.y, m2.y);
                }
                *(float2*)&C[(size_t)r2 * 128 + c1] = v;
            }
        }
    }
}

// ---------------- launch ----------------
extern "C" void kernel_launch(void* const* d_in, const int* in_sizes, int n_in,
                              void* d_out, int out_size) {
    const float* x   = (const float*)d_in[0];
    const int*   ei  = (const int*)d_in[1];
    const float* ew  = (const float*)d_in[2];
    const float* W0  = (const float*)d_in[3];
    const float* a0s = (const float*)d_in[4];
    const float* a0d = (const float*)d_in[5];
    const float* W1  = (const float*)d_in[6];
    const float* a1s = (const float*)d_in[7];
    const float* a1d = (const float*)d_in[8];
    const float* gW1 = (const float*)d_in[10];
    const float* gW0 = (const float*)d_in[9];
    float* out = (float*)d_out;

    float *pWh0, *pHg, *pX2b;
    __nv_bfloat16 *pYh, *pYl, *pXh, *pXl, *pX2h, *pX2l;
    __nv_bfloat16 *pBth, *pBtl, *pB0h, *pB0l, *pBg0h, *pBg0l, *pBg1h, *pBg1l;
    cudaGetSymbolAddress((void**)&pWh0,  g_Wh0);
    cudaGetSymbolAddress((void**)&pHg,   g_hg);
    cudaGetSymbolAddress((void**)&pX2b,  g_x2b);
    cudaGetSymbolAddress((void**)&pYh,   g_yh);
    cudaGetSymbolAddress((void**)&pYl,   g_yl);
    cudaGetSymbolAddress((void**)&pXh,   g_xh);
    cudaGetSymbolAddress((void**)&pXl,   g_xl);
    cudaGetSymbolAddress((void**)&pX2h,  g_x2h);
    cudaGetSymbolAddress((void**)&pX2l,  g_x2l);
    cudaGetSymbolAddress((void**)&pBth,  g_Bth);
    cudaGetSymbolAddress((void**)&pBtl,  g_Btl);
    cudaGetSymbolAddress((void**)&pB0h,  g_B0h);
    cudaGetSymbolAddress((void**)&pB0l,  g_B0l);
    cudaGetSymbolAddress((void**)&pBg0h, g_Bg0h);
    cudaGetSymbolAddress((void**)&pBg0l, g_Bg0l);
    cudaGetSymbolAddress((void**)&pBg1h, g_Bg1h);
    cudaGetSymbolAddress((void**)&pBg1l, g_Bg1l);

    const int gA = (Nn + 127) / 128;
    const int gS = (Nn + 1023) / 1024;   // 49
    const int SMEM_TC = 2 * BUF_BYTES;   // 147456 bytes
    cudaFuncSetAttribute(gemm_tc, cudaFuncAttributeMaxDynamicSharedMemorySize, SMEM_TC);

    // edge-index normalization + CSR build (parallel scan)
    k_detect <<<1, 32>>>(ei);
    k_zero   <<<(Nn + 255) / 256, 256>>>();
    k_convcnt<<<(Ee + 255) / 256, 256>>>(ei);
    k_scan1  <<<gS, 1024>>>();
    k_scan2  <<<1, 64>>>();
    k_scan3  <<<gS, 1024>>>();
    k_scatter<<<(Ee + 255) / 256, 256>>>(ew);
    k_normw  <<<Nn, 128>>>();

    // input split + weight packs
    k_splitx    <<<(Nn * Dd + 255) / 256, 256>>>(x);
    k_packW0split<<<(128 * 128 + 255) / 256, 256>>>(W0);
    k_packWsplit<<<(128 * 128 + 255) / 256, 256>>>(gW0, pBg0h, pBg0l);
    k_packWsplit<<<(128 * 128 + 255) / 256, 256>>>(gW1, pBg1h, pBg1l);
    k_packW1    <<<(128 * 1024 + 255) / 256, 256>>>(W1);

    // GAT layer 0
    gemm_tc  <<<gA, 256, SMEM_TC>>>(pXh, pXl, pB0h, pB0l, pWh0, (const float*)0, 1.f, Nn, 128);
    k_esed0  <<<(Nn * Hh + 255) / 256, 256>>>(a0s, a0d);
    k_att    <<<(Nn + 7) / 8, 256>>>();
    k_agg_gat0<<<Nn, 128>>>();

    // GCN layer 0
    gemm_tc  <<<gA, 256, SMEM_TC>>>(pXh, pXl, pBg0h, pBg0l, pHg, (const float*)0, 1.f, Nn, 128);
    k_agg_gcn<<<Nn, 128>>>(pHg, (float*)0, pX2h, pX2l, 1);

    // GCN layer 1 (moved before GAT-L1 GEMM so the final max can fuse)
    gemm_tc  <<<gA, 256, SMEM_TC>>>(pX2h, pX2l, pBg1h, pBg1l, pHg, (const float*)0, 1.f, Nn, 128);
    k_agg_gcn<<<Nn, 128>>>(pHg, pX2b, (__nv_bfloat16*)0, (__nv_bfloat16*)0, 0);

    // GAT layer 1: aggregate (split-bf16), then tensor GEMM with fused max(out, x2b)
    k_uv1    <<<4, 256>>>(W1, a1s, a1d);
    k_esed1  <<<(Nn + 15) / 16, 512>>>();
    k_att    <<<(Nn + 7) / 8, 256>>>();
    k_agg_gat1<<<Nn, 128>>>();
    gemm_tc  <<<gA, 256, SMEM_TC>>>(pYh, pYl, pBth, pBtl, out, pX2b, 0.125f, Nn, 1024);
}